// round 15
// baseline (speedup 1.0000x reference)
#include <cuda_runtime.h>
#include <cstdint>

#define NN 100000
#define NE 1600000
#define DIN 128
#define DHID 128
#define NCLS 64

// ---------------- device scratch — referenced ONLY from device code ---------
__device__ __align__(16) float r15_h[(size_t)NN * 128];
__device__ __align__(16) float r15_a[(size_t)NN * 128];
__device__ __align__(16) float r15_dinv[NN];
__device__ __align__(16) int   r15_cnt[NN];
__device__ __align__(16) int   r15_rs[NN];
__device__ __align__(16) int   r15_wcur[NN];
__device__ __align__(16) int   r15_col[NE];
__device__ __align__(16) int   r15_bsum[256];
__device__ int r15_fail;

__global__ void r15_init() { if (threadIdx.x == 0) r15_fail = 0; }

// ---------------- graph build (int32 PLANAR per R13 measurement) ------------
__global__ void r15_zcnt(int n) {
    int i = blockIdx.x * blockDim.x + threadIdx.x;
    if (i < n) r15_cnt[i] = 0;
}
__global__ void r15_hist(const int* __restrict__ ep, int e, int n) {
    int i = blockIdx.x * blockDim.x + threadIdx.x;
    if (i < e) {
        int d = ep[e + i];
        if (d >= 0 && d < n) atomicAdd(&r15_cnt[d], 1);
    }
}
__global__ void r15_dinvk(int n) {
    int i = blockIdx.x * blockDim.x + threadIdx.x;
    if (i < n) r15_dinv[i] = rsqrtf((float)(r15_cnt[i] + 1));   // +1 self loop
}
__global__ void r15_scan1(int n) {
    __shared__ int s[1024];
    int lid = threadIdx.x, gid = blockIdx.x * 1024 + lid;
    int v = (gid < n) ? r15_cnt[gid] : 0;
    s[lid] = v; __syncthreads();
    for (int off = 1; off < 1024; off <<= 1) {
        int t = (lid >= off) ? s[lid - off] : 0;
        __syncthreads(); s[lid] += t; __syncthreads();
    }
    if (gid < n) r15_rs[gid] = s[lid] - v;
    if (lid == 1023) r15_bsum[blockIdx.x] = s[1023];
}
__global__ void r15_scan2(int nb) {
    __shared__ int s[256];
    int lid = threadIdx.x;
    int v = (lid < nb) ? r15_bsum[lid] : 0;
    s[lid] = v; __syncthreads();
    for (int off = 1; off < 256; off <<= 1) {
        int t = (lid >= off) ? s[lid - off] : 0;
        __syncthreads(); s[lid] += t; __syncthreads();
    }
    if (lid < nb) r15_bsum[lid] = s[lid] - v;
}
__global__ void r15_scan3(int n) {
    int gid = blockIdx.x * 1024 + threadIdx.x;
    if (gid < n) {
        int r = r15_rs[gid] + r15_bsum[blockIdx.x];
        r15_rs[gid] = r; r15_wcur[gid] = r;
    }
}
__global__ void r15_fill(const int* __restrict__ ep, int e, int n) {
    int i = blockIdx.x * blockDim.x + threadIdx.x;
    if (i < e) {
        int s = ep[i], d = ep[e + i];
        if (d >= 0 && d < n && s >= 0 && s < n) {
            int pos = atomicAdd(&r15_wcur[d], 1);
            if (pos >= 0 && pos < NE) r15_col[pos] = s;
        }
    }
}

// ---------------- GEMM: dest/source are SYMBOLS, never host-passed ----------
// SRC=0: X from param (harness pointer). SRC=1: X = r15_a (device symbol).
// out[row,:] = dinv[row] * (X[row,:] @ W)
template <int BN, int NCH, int SRC>
__global__ void __launch_bounds__(256) r15_gemm(
    const float* __restrict__ Xparam, const float* __restrict__ W, int nrows)
{
    constexpr int BM = 128, BK = 16;
    __shared__ float Xs[BK][BM + 1];
    __shared__ float Ws[BK][BN];
    const float* X = (SRC == 0) ? Xparam : r15_a;
    float* out = r15_h;

    int t = threadIdx.x, rg = t >> 4, cg = t & 15;
    int blockRow = blockIdx.x * BM;

    float acc[8][4 * NCH];
#pragma unroll
    for (int i = 0; i < 8; i++)
#pragma unroll
        for (int j = 0; j < 4 * NCH; j++) acc[i][j] = 0.f;

    for (int kb = 0; kb < 128; kb += BK) {
#pragma unroll
        for (int it = 0; it < 2; it++) {
            int f = t + it * 256, row = f >> 2, kq = (f & 3) * 4;
            float4 v = make_float4(0.f, 0.f, 0.f, 0.f);
            int gr = blockRow + row;
            if (gr < nrows)
                v = *reinterpret_cast<const float4*>(X + (size_t)gr * 128 + kb + kq);
            Xs[kq + 0][row] = v.x; Xs[kq + 1][row] = v.y;
            Xs[kq + 2][row] = v.z; Xs[kq + 3][row] = v.w;
        }
#pragma unroll
        for (int it = 0; it < (BK * BN) / 256; it++) {
            int f = t + it * 256;
            Ws[f / BN][f % BN] = W[(size_t)(kb + f / BN) * BN + f % BN];
        }
        __syncthreads();
#pragma unroll
        for (int k = 0; k < BK; k++) {
            float av[8];
#pragma unroll
            for (int i = 0; i < 4; i++) {
                av[i] = Xs[k][rg * 4 + i];
                av[i + 4] = Xs[k][64 + rg * 4 + i];
            }
            float bv[4 * NCH];
#pragma unroll
            for (int h = 0; h < NCH; h++)
#pragma unroll
                for (int j = 0; j < 4; j++)
                    bv[h * 4 + j] = Ws[k][h * 64 + cg * 4 + j];
#pragma unroll
            for (int i = 0; i < 8; i++)
#pragma unroll
                for (int j = 0; j < 4 * NCH; j++)
                    acc[i][j] += av[i] * bv[j];
        }
        __syncthreads();
    }
#pragma unroll
    for (int i = 0; i < 8; i++) {
        int row = blockRow + ((i < 4) ? (rg * 4 + i) : (64 + rg * 4 + i - 4));
        if (row < nrows) {
            float di = r15_dinv[row];
#pragma unroll
            for (int h = 0; h < NCH; h++) {
                float4 v;
                v.x = acc[i][h * 4 + 0] * di; v.y = acc[i][h * 4 + 1] * di;
                v.z = acc[i][h * 4 + 2] * di; v.w = acc[i][h * 4 + 3] * di;
                *reinterpret_cast<float4*>(out + (size_t)row * BN + h * 64 + cg * 4) = v;
            }
        }
    }
}

// ---------------- aggregations (symbols only) --------------------------------
__global__ void __launch_bounds__(256) r15_agg1(const float* __restrict__ b1, int n) {
    int warp = (blockIdx.x * blockDim.x + threadIdx.x) >> 5;
    int lane = threadIdx.x & 31;
    if (warp >= n) return;
    int i = warp, c0 = lane * 4;
    float4 acc = *reinterpret_cast<const float4*>(r15_h + (size_t)i * 128 + c0);
    int start = r15_rs[i], deg = r15_cnt[i];
    for (int j = 0; j < deg; j += 32) {
        int c = (j + lane < deg) ? r15_col[start + j + lane] : 0;
        int m = min(32, deg - j);
        for (int jj = 0; jj < m; jj++) {
            int s = __shfl_sync(0xffffffffu, c, jj);
            float4 v = *reinterpret_cast<const float4*>(r15_h + (size_t)s * 128 + c0);
            acc.x += v.x; acc.y += v.y; acc.z += v.z; acc.w += v.w;
        }
    }
    float di = r15_dinv[i];
    float4 bb = *reinterpret_cast<const float4*>(b1 + c0);
    float4 r;
    r.x = fmaxf(acc.x * di + bb.x, 0.f); r.y = fmaxf(acc.y * di + bb.y, 0.f);
    r.z = fmaxf(acc.z * di + bb.z, 0.f); r.w = fmaxf(acc.w * di + bb.w, 0.f);
    *reinterpret_cast<float4*>(r15_a + (size_t)i * 128 + c0) = r;
}

__global__ void __launch_bounds__(256) r15_agg2(const float* __restrict__ b2,
                                                float* __restrict__ out, int n) {
    int warp = (blockIdx.x * blockDim.x + threadIdx.x) >> 5;
    int lane = threadIdx.x & 31;
    if (warp >= n) return;
    int i = warp, c0 = lane * 2;
    float2 acc = *reinterpret_cast<const float2*>(r15_h + (size_t)i * 64 + c0);
    int start = r15_rs[i], deg = r15_cnt[i];
    for (int j = 0; j < deg; j += 32) {
        int c = (j + lane < deg) ? r15_col[start + j + lane] : 0;
        int m = min(32, deg - j);
        for (int jj = 0; jj < m; jj++) {
            int s = __shfl_sync(0xffffffffu, c, jj);
            float2 v = *reinterpret_cast<const float2*>(r15_h + (size_t)s * 64 + c0);
            acc.x += v.x; acc.y += v.y;
        }
    }
    float di = r15_dinv[i];
    float2 bb = *reinterpret_cast<const float2*>(b2 + c0);
    float vx = acc.x * di + bb.x, vy = acc.y * di + bb.y;
    float mx = fmaxf(vx, vy);
#pragma unroll
    for (int off = 16; off > 0; off >>= 1)
        mx = fmaxf(mx, __shfl_xor_sync(0xffffffffu, mx, off));
    float s = expf(vx - mx) + expf(vy - mx);
#pragma unroll
    for (int off = 16; off > 0; off >>= 1)
        s += __shfl_xor_sync(0xffffffffu, s, off);
    float lse = mx + logf(s);
    out[(size_t)i * 64 + c0]     = vx - lse;
    out[(size_t)i * 64 + c0 + 1] = vy - lse;
}

// ---------------- slim self-check + mux (insurance) --------------------------
__global__ void r15_chk(int which, int code) {
    __shared__ int nz;
    if (threadIdx.x == 0) nz = 0;
    __syncthreads();
    const float* p = which ? r15_a : r15_h;
    for (int i = threadIdx.x; i < 4096; i += 256)
        if (p[(long long)i * 1562] != 0.f) { nz = 1; break; }
    __syncthreads();
    if (threadIdx.x == 0 && nz == 0 && r15_fail == 0) r15_fail = code;
}
__global__ void r15_mux(float* __restrict__ out, long long cnt) {
    int f = r15_fail;
    if (f == 0) return;
    long long i = (long long)blockIdx.x * blockDim.x + threadIdx.x;
    if (i < cnt) out[i] = -4.1588831f * (1.f + 2.0f * (float)f);
}

// ---------------- launch ------------------------------------------------------
extern "C" void kernel_launch(void* const* d_in, const int* in_sizes, int n_in,
                              void* d_out, int out_size) {
    const float *x = nullptr, *W1 = nullptr, *b1 = nullptr, *W2 = nullptr, *b2 = nullptr;
    const int* ep = nullptr; int S = 0;
    for (int i = 0; i < n_in; i++) {
        int s = in_sizes[i];
        if      (s == NN * DIN)    x  = (const float*)d_in[i];
        else if (s == DIN * DHID)  W1 = (const float*)d_in[i];
        else if (s == DHID * NCLS) W2 = (const float*)d_in[i];
        else if (s == DHID)        b1 = (const float*)d_in[i];
        else if (s == NCLS)        b2 = (const float*)d_in[i];
        else if (!ep)              { ep = (const int*)d_in[i]; S = s; }
    }
    float* out = (float*)d_out;
    long long outCnt = (long long)out_size;
    int outBlocks = (int)((outCnt + 255) / 256);
    if (!x || !W1 || !b1 || !W2 || !b2 || !ep || S < 2) return;

    int e = S / 2, n = NN;
    int nb = (n + 1023) / 1024;

    r15_init<<<1, 32>>>();
    r15_zcnt<<<(n + 255) / 256, 256>>>(n);
    r15_hist<<<(e + 255) / 256, 256>>>(ep, e, n);
    r15_dinvk<<<(n + 255) / 256, 256>>>(n);
    r15_scan1<<<nb, 1024>>>(n);
    r15_scan2<<<1, 256>>>(nb);
    r15_scan3<<<nb, 1024>>>(n);
    r15_fill<<<(e + 255) / 256, 256>>>(ep, e, n);

    int gblocks = (n + 127) / 128;
    r15_gemm<128, 2, 0><<<gblocks, 256>>>(x, W1, n);       // h = dinv*(x@W1)
    r15_chk<<<1, 256>>>(0, 1);
    r15_agg1<<<(n + 7) / 8, 256>>>(b1, n);                 // a = relu(dinv*agg+b1)
    r15_chk<<<1, 256>>>(1, 2);
    r15_gemm<64, 1, 1><<<gblocks, 256>>>(nullptr, W2, n);  // h = dinv*(a@W2)
    r15_agg2<<<(n + 7) / 8, 256>>>(b2, out, n);            // out = log_softmax
    r15_mux<<<outBlocks, 256>>>(out, outCnt);
}